// round 16
// baseline (speedup 1.0000x reference)
#include <cuda_runtime.h>
#include <cuda_bf16.h>
#include <cuda_fp16.h>
#include <cstdint>

#define N_NODES 100000
#define F_IN    64
#define HID     128
#define E_MAX   1700000
#define ELL_W   64

// ---------------------------------------------------------------------------
// Scratch (device globals — no runtime allocation)
// ---------------------------------------------------------------------------
__device__ __align__(16) __half g_xf[N_NODES * F_IN];          // x fp16
__device__ __align__(16) __half g_hf[N_NODES * HID];           // h fp16
__device__ __align__(16) __half g_B1h[128 * 128];              // [Wl1|Wr1] fp16 hi
__device__ __align__(16) __half g_B1l[128 * 128];              // fp16 lo (residual)
__device__ __align__(16) __half g_B2h[128 * 256];
__device__ __align__(16) __half g_B2l[128 * 256];
__device__ int g_deg[N_NODES];
__device__ int g_ell[(size_t)N_NODES * ELL_W];                 // 25.6 MB

// ---------------------------------------------------------------------------
__device__ __forceinline__ uint32_t smem_u32(const void* p) {
    return (uint32_t)__cvta_generic_to_shared(p);
}

#define CP_ASYNC16(dst, src) \
    asm volatile("cp.async.cg.shared.global [%0], [%1], 16;" :: "r"(dst), "l"(src))
#define CP_COMMIT() asm volatile("cp.async.commit_group;" ::: "memory")
#define CP_WAIT(n)  asm volatile("cp.async.wait_group %0;" :: "n"(n) : "memory")

#define LDSM4(r0, r1, r2, r3, addr) \
    asm volatile("ldmatrix.sync.aligned.m8n8.x4.shared.b16 {%0,%1,%2,%3}, [%4];" \
                 : "=r"(r0), "=r"(r1), "=r"(r2), "=r"(r3) : "r"(addr))

#define MMA16816F(d, a, b0, b1) \
    asm volatile("mma.sync.aligned.m16n8k16.row.col.f32.f16.f16.f32 " \
                 "{%0,%1,%2,%3}, {%4,%5,%6,%7}, {%8,%9}, {%0,%1,%2,%3};" \
                 : "+f"((d)[0]), "+f"((d)[1]), "+f"((d)[2]), "+f"((d)[3]) \
                 : "r"((a)[0]), "r"((a)[1]), "r"((a)[2]), "r"((a)[3]), \
                   "r"(b0), "r"(b1))

// ---------------------------------------------------------------------------
__global__ void zero_deg() {
    int i = blockIdx.x * blockDim.x + threadIdx.x;
    if (i < N_NODES) g_deg[i] = 0;
}

// ---------------------------------------------------------------------------
// Fused prep + ELL build (disjoint thread ranges)
// ---------------------------------------------------------------------------
#define NCVT (N_NODES * 8)
#define WTOT (128 * 128 + 128 * 256)
__global__ void prep_build(const float4* __restrict__ x4, __half* __restrict__ xf,
                           const float* __restrict__ WL1, const float* __restrict__ WR1,
                           const float* __restrict__ WL2, const float* __restrict__ WR2,
                           const int* __restrict__ ei, int E) {
    int idx = blockIdx.x * blockDim.x + threadIdx.x;
    if (idx < NCVT) {
        float4 v0 = __ldg(x4 + idx * 2);
        float4 v1 = __ldg(x4 + idx * 2 + 1);
        uint4 o;
        __half2* p = reinterpret_cast<__half2*>(&o);
        p[0] = __floats2half2_rn(v0.x, v0.y);
        p[1] = __floats2half2_rn(v0.z, v0.w);
        p[2] = __floats2half2_rn(v1.x, v1.y);
        p[3] = __floats2half2_rn(v1.z, v1.w);
        *reinterpret_cast<uint4*>(xf + (size_t)idx * 8) = o;
        return;
    }
    int widx = idx - NCVT;
    if (widx < 128 * 128) {                     // layer 1, K = 128
        int n = widx >> 7, k = widx & 127;
        float v = (k < 64) ? __ldg(WL1 + n * 64 + k) : __ldg(WR1 + n * 64 + (k - 64));
        __half hi = __float2half_rn(v);
        __half lo = __float2half_rn(v - __half2float(hi));
        g_B1h[widx] = hi;
        g_B1l[widx] = lo;
        return;
    }
    if (widx < WTOT) {                          // layer 2, K = 256
        int j = widx - 128 * 128;
        int n = j >> 8, k = j & 255;
        float v = (k < 128) ? __ldg(WL2 + n * 128 + k) : __ldg(WR2 + n * 128 + (k - 128));
        __half hi = __float2half_rn(v);
        __half lo = __float2half_rn(v - __half2float(hi));
        g_B2h[j] = hi;
        g_B2l[j] = lo;
        return;
    }
    // ---- edge scatter ----
    int t  = idx - NCVT - WTOT;
    int e0 = t * 4;
    if (e0 >= E) return;
    int s[4], d[4], cnt;
    if (((E & 3) == 0) && (e0 + 3 < E)) {
        int4 s4 = __ldg(reinterpret_cast<const int4*>(ei) + t);
        int4 d4 = __ldg(reinterpret_cast<const int4*>(ei + E) + t);
        s[0] = s4.x; s[1] = s4.y; s[2] = s4.z; s[3] = s4.w;
        d[0] = d4.x; d[1] = d4.y; d[2] = d4.z; d[3] = d4.w;
        cnt = 4;
    } else {
        cnt = E - e0;
        if (cnt > 4) cnt = 4;
        for (int j = 0; j < cnt; ++j) {
            s[j] = __ldg(ei + e0 + j);
            d[j] = __ldg(ei + E + e0 + j);
        }
    }
#pragma unroll
    for (int j = 0; j < 4; ++j) {
        if (j < cnt) {
            int rank = atomicAdd(&g_deg[d[j]], 1);
            if (rank < ELL_W)
                g_ell[(size_t)d[j] * ELL_W + rank] = s[j];
        }
    }
}

// ---------------------------------------------------------------------------
// FUSED gather + GEMM.
//   A (virtual, K halfs) = [mean(Aroot neighbors) | Aroot], computed per CTA:
//     - mean half gathered in-kernel from g_ell/g_deg into smem (fp32 accum)
//     - root half + ALL B stages via cp.async (issued before gather => overlap)
//   Mainloop reads only smem (no per-stage syncs).
//   D = A @ Whi^T + A @ Wlo^T ; epilogue: LAYER1 -> relu -> hf fp16, else fp32 out.
//   smem: A stages NT x 16KB | B stages NT x (hi 16KB + lo 16KB)
// ---------------------------------------------------------------------------
template <int K, bool LAYER1>
__global__ void __launch_bounds__(256)
sage_fused(const __half* __restrict__ Aroot,   // xf (L1) or hf (L2); row = K/2 halfs
           const __half* __restrict__ Bh,
           const __half* __restrict__ Bl,
           const float* __restrict__ bias,
           float* __restrict__ outF,
           __half* __restrict__ outH,
           int M) {
    constexpr int NT     = K / 64;       // 2 or 4 stages
    constexpr int NMEAN  = NT / 2;       // mean-half stages
    constexpr int CH     = (K / 2) / 8;  // uint4 chunks per source row: 8 or 16
    constexpr int ABYTES = NT * 16384;

    extern __shared__ char smem[];
    const uint32_t sbase = smem_u32(smem);

    const int tid     = threadIdx.x;
    const int block_m = blockIdx.x * 128;
    const int warp    = tid >> 5;
    const int lane    = tid & 31;
    const int wm      = warp & 3;
    const int wn      = warp >> 2;

    // ---- 1. cp.async: root-half A stages ----
#pragma unroll
    for (int kt = NMEAN; kt < NT; ++kt) {
        char* dst = smem + kt * 16384;
        const int colb = (kt - NMEAN) * 128;
#pragma unroll
        for (int j = 0; j < 4; ++j) {
            int c = j * 256 + tid;
            int row = c >> 3, ch = c & 7;
            int grow = block_m + row;
            if (grow >= M) grow = M - 1;
            const char* src = reinterpret_cast<const char*>(Aroot) +
                              (size_t)grow * K + colb + ch * 16;
            int off = row * 128 + ((ch ^ (row & 7)) << 4);
            CP_ASYNC16(smem_u32(dst + off), src);
        }
    }
    // ---- 2. cp.async: all B stages (hi + lo) ----
#pragma unroll
    for (int kt = 0; kt < NT; ++kt) {
        char* dst = smem + ABYTES + kt * 32768;
#pragma unroll
        for (int j = 0; j < 4; ++j) {
            int c = j * 256 + tid;
            int n = c >> 3, ch = c & 7;
            int off = n * 128 + ((ch ^ (n & 7)) << 4);
            const char* sh = reinterpret_cast<const char*>(Bh) +
                             (size_t)n * 2 * K + kt * 128 + ch * 16;
            CP_ASYNC16(smem_u32(dst + off), sh);
            const char* sl = reinterpret_cast<const char*>(Bl) +
                             (size_t)n * 2 * K + kt * 128 + ch * 16;
            CP_ASYNC16(smem_u32(dst + 16384 + off), sl);
        }
    }
    CP_COMMIT();

    // ---- 3. gather mean half into A smem (overlaps the cp.asyncs) ----
    {
        const uint4* srcU4 = reinterpret_cast<const uint4*>(Aroot);
#pragma unroll
        for (int it = 0; it < (128 * CH) / 256; ++it) {
            int item = it * 256 + tid;
            int row = item / CH;
            int c   = item % CH;
            int n = block_m + row;
            if (n >= M) n = M - 1;
            int dg  = __ldg(g_deg + n);
            int cnt2 = dg < ELL_W ? dg : ELL_W;
            const int* erow = g_ell + (size_t)n * ELL_W;

            float acc[8];
#pragma unroll
            for (int j = 0; j < 8; ++j) acc[j] = 0.f;

            auto accum = [&](uint4 v) {
                const __half2* p = reinterpret_cast<const __half2*>(&v);
#pragma unroll
                for (int w = 0; w < 4; ++w) {
                    float2 f = __half22float2(p[w]);
                    acc[2 * w + 0] += f.x;
                    acc[2 * w + 1] += f.y;
                }
            };

            int i = 0;
            for (; i + 4 <= cnt2; i += 4) {
                int s0 = __ldg(erow + i),     s1 = __ldg(erow + i + 1);
                int s2 = __ldg(erow + i + 2), s3 = __ldg(erow + i + 3);
                uint4 v0 = __ldg(srcU4 + (size_t)s0 * CH + c);
                uint4 v1 = __ldg(srcU4 + (size_t)s1 * CH + c);
                uint4 v2 = __ldg(srcU4 + (size_t)s2 * CH + c);
                uint4 v3 = __ldg(srcU4 + (size_t)s3 * CH + c);
                accum(v0); accum(v1); accum(v2); accum(v3);
            }
            for (; i < cnt2; ++i)
                accum(__ldg(srcU4 + (size_t)__ldg(erow + i) * CH + c));

            float inv = 1.0f / fmaxf((float)dg, 1.0f);
            uint4 o;
            __half2* p = reinterpret_cast<__half2*>(&o);
#pragma unroll
            for (int w = 0; w < 4; ++w)
                p[w] = __floats2half2_rn(acc[2 * w] * inv, acc[2 * w + 1] * inv);

            int kt = c >> 3, ch = c & 7;
            *reinterpret_cast<uint4*>(
                smem + kt * 16384 + row * 128 + ((ch ^ (row & 7)) << 4)) = o;
        }
    }

    CP_WAIT(0);
    __syncthreads();

    // ---- 4. mainloop: all operands in smem, no further syncs ----
    float d[2][8][4];
#pragma unroll
    for (int i = 0; i < 2; ++i)
#pragma unroll
        for (int j = 0; j < 8; ++j)
#pragma unroll
            for (int q = 0; q < 4; ++q) d[i][j][q] = 0.f;

#pragma unroll
    for (int kt = 0; kt < NT; ++kt) {
        const uint32_t sA  = sbase + kt * 16384;
        const uint32_t sBh = sbase + ABYTES + kt * 32768;
        const uint32_t sBl = sBh + 16384;

#pragma unroll
        for (int kk = 0; kk < 4; ++kk) {
            uint32_t a[2][4];
#pragma unroll
            for (int mt = 0; mt < 2; ++mt) {
                int row = wm * 32 + mt * 16 + (lane & 15);
                int ch  = kk * 2 + (lane >> 4);
                int off = row * 128 + ((ch ^ (row & 7)) << 4);
                LDSM4(a[mt][0], a[mt][1], a[mt][2], a[mt][3], sA + off);
            }
            uint32_t bh[4][4], bl[4][4];
#pragma unroll
            for (int nt2 = 0; nt2 < 4; ++nt2) {
                int row = wn * 64 + nt2 * 16 + (lane & 15);
                int ch  = kk * 2 + (lane >> 4);
                int off = row * 128 + ((ch ^ (row & 7)) << 4);
                LDSM4(bh[nt2][0], bh[nt2][1], bh[nt2][2], bh[nt2][3], sBh + off);
                LDSM4(bl[nt2][0], bl[nt2][1], bl[nt2][2], bl[nt2][3], sBl + off);
            }
#pragma unroll
            for (int mt = 0; mt < 2; ++mt)
#pragma unroll
                for (int nt = 0; nt < 8; ++nt) {
                    int nt2 = nt >> 1, o = nt & 1;
                    MMA16816F(d[mt][nt], a[mt], bh[nt2][o], bh[nt2][o + 2]);
                    MMA16816F(d[mt][nt], a[mt], bl[nt2][o], bl[nt2][o + 2]);
                }
        }
    }

    // ---- 5. epilogue ----
    const int r0base = block_m + wm * 32 + (lane >> 2);
    const int cbase  = wn * 64 + (lane & 3) * 2;
#pragma unroll
    for (int mt = 0; mt < 2; ++mt) {
#pragma unroll
        for (int nt = 0; nt < 8; ++nt) {
            int c = cbase + nt * 8;
            float b0 = __ldg(bias + c);
            float b1 = __ldg(bias + c + 1);
#pragma unroll
            for (int half = 0; half < 2; ++half) {
                int row = r0base + mt * 16 + half * 8;
                if (row >= M) continue;
                float o0 = d[mt][nt][half * 2 + 0] + b0;
                float o1 = d[mt][nt][half * 2 + 1] + b1;
                if (LAYER1) {
                    o0 = fmaxf(o0, 0.f);
                    o1 = fmaxf(o1, 0.f);
                    *reinterpret_cast<__half2*>(outH + (size_t)row * 128 + c) =
                        __floats2half2_rn(o0, o1);
                } else {
                    *reinterpret_cast<float2*>(outF + (size_t)row * 128 + c) =
                        make_float2(o0, o1);
                }
            }
        }
    }
}

// ---------------------------------------------------------------------------
extern "C" void kernel_launch(void* const* d_in, const int* in_sizes, int n_in,
                              void* d_out, int out_size) {
    const float* x   = (const float*)d_in[0];
    const int*   ei  = (const int*)  d_in[1];
    const float* Wl1 = (const float*)d_in[2];
    const float* bl1 = (const float*)d_in[3];
    const float* Wr1 = (const float*)d_in[4];
    const float* Wl2 = (const float*)d_in[5];
    const float* bl2 = (const float*)d_in[6];
    const float* Wr2 = (const float*)d_in[7];
    float* out = (float*)d_out;

    const int E = in_sizes[1] / 2;
    const int M = N_NODES;

    __half *xf, *hf, *b1h, *b1l, *b2h, *b2l;
    cudaGetSymbolAddress((void**)&xf,  g_xf);
    cudaGetSymbolAddress((void**)&hf,  g_hf);
    cudaGetSymbolAddress((void**)&b1h, g_B1h);
    cudaGetSymbolAddress((void**)&b1l, g_B1l);
    cudaGetSymbolAddress((void**)&b2h, g_B2h);
    cudaGetSymbolAddress((void**)&b2l, g_B2l);

    static bool attr_done = false;
    if (!attr_done) {
        cudaFuncSetAttribute(sage_fused<128, true>,
                             cudaFuncAttributeMaxDynamicSharedMemorySize, 98304);
        cudaFuncSetAttribute(sage_fused<256, false>,
                             cudaFuncAttributeMaxDynamicSharedMemorySize, 196608);
        attr_done = true;
    }

    const int gemm_blocks = (M + 127) / 128;
    const long pb_threads = (long)NCVT + WTOT + (E + 3) / 4;

    zero_deg<<<(N_NODES + 255) / 256, 256>>>();
    prep_build<<<(pb_threads + 255) / 256, 256>>>(
        reinterpret_cast<const float4*>(x), xf, Wl1, Wr1, Wl2, Wr2, ei, E);

    // layer 1 (fused gather + GEMM)
    sage_fused<128, true><<<gemm_blocks, 256, 98304>>>(
        xf, b1h, b1l, bl1, nullptr, hf, M);

    // layer 2 (fused gather + GEMM)
    sage_fused<256, false><<<gemm_blocks, 256, 196608>>>(
        hf, b2h, b2l, bl2, out, nullptr, M);
}

// round 17
// speedup vs baseline: 1.4892x; 1.4892x over previous
#include <cuda_runtime.h>
#include <cuda_bf16.h>
#include <cuda_fp16.h>
#include <cstdint>

#define N_NODES 100000
#define F_IN    64
#define HID     128
#define E_MAX   1700000
#define ELL_W   64

// ---------------------------------------------------------------------------
// Scratch (device globals — no runtime allocation)
// ---------------------------------------------------------------------------
__device__ __align__(16) __half g_xf[N_NODES * F_IN];          // x fp16
__device__ __align__(16) __half g_hf[N_NODES * HID];           // h fp16
__device__ __align__(16) __half g_m2[N_NODES * HID];           // mean(h) fp16
__device__ __align__(16) __half g_B1h[128 * 128];              // [Wl1|Wr1] fp16 hi
__device__ __align__(16) __half g_B1l[128 * 128];              // fp16 lo (residual)
__device__ __align__(16) __half g_B2h[128 * 256];
__device__ __align__(16) __half g_B2l[128 * 256];
__device__ int g_deg[N_NODES];
__device__ int g_ell[(size_t)N_NODES * ELL_W];                 // 25.6 MB

// ---------------------------------------------------------------------------
__device__ __forceinline__ uint32_t smem_u32(const void* p) {
    return (uint32_t)__cvta_generic_to_shared(p);
}

#define CP_ASYNC16(dst, src) \
    asm volatile("cp.async.cg.shared.global [%0], [%1], 16;" :: "r"(dst), "l"(src))
#define CP_COMMIT() asm volatile("cp.async.commit_group;" ::: "memory")
#define CP_WAIT(n)  asm volatile("cp.async.wait_group %0;" :: "n"(n) : "memory")

#define LDSM4(r0, r1, r2, r3, addr) \
    asm volatile("ldmatrix.sync.aligned.m8n8.x4.shared.b16 {%0,%1,%2,%3}, [%4];" \
                 : "=r"(r0), "=r"(r1), "=r"(r2), "=r"(r3) : "r"(addr))

#define MMA16816F(d, a, b0, b1) \
    asm volatile("mma.sync.aligned.m16n8k16.row.col.f32.f16.f16.f32 " \
                 "{%0,%1,%2,%3}, {%4,%5,%6,%7}, {%8,%9}, {%0,%1,%2,%3};" \
                 : "+f"((d)[0]), "+f"((d)[1]), "+f"((d)[2]), "+f"((d)[3]) \
                 : "r"((a)[0]), "r"((a)[1]), "r"((a)[2]), "r"((a)[3]), \
                   "r"(b0), "r"(b1))

// ---------------------------------------------------------------------------
__global__ void zero_deg() {
    int i = blockIdx.x * blockDim.x + threadIdx.x;
    if (i < N_NODES) g_deg[i] = 0;
}

// ---------------------------------------------------------------------------
// Fused prep + ELL build (disjoint thread ranges)
// ---------------------------------------------------------------------------
#define NCVT (N_NODES * 8)
#define WTOT (128 * 128 + 128 * 256)
__global__ void prep_build(const float4* __restrict__ x4, __half* __restrict__ xf,
                           const float* __restrict__ WL1, const float* __restrict__ WR1,
                           const float* __restrict__ WL2, const float* __restrict__ WR2,
                           const int* __restrict__ ei, int E) {
    int idx = blockIdx.x * blockDim.x + threadIdx.x;
    if (idx < NCVT) {
        float4 v0 = __ldg(x4 + idx * 2);
        float4 v1 = __ldg(x4 + idx * 2 + 1);
        uint4 o;
        __half2* p = reinterpret_cast<__half2*>(&o);
        p[0] = __floats2half2_rn(v0.x, v0.y);
        p[1] = __floats2half2_rn(v0.z, v0.w);
        p[2] = __floats2half2_rn(v1.x, v1.y);
        p[3] = __floats2half2_rn(v1.z, v1.w);
        *reinterpret_cast<uint4*>(xf + (size_t)idx * 8) = o;
        return;
    }
    int widx = idx - NCVT;
    if (widx < 128 * 128) {                     // layer 1, K = 128
        int n = widx >> 7, k = widx & 127;
        float v = (k < 64) ? __ldg(WL1 + n * 64 + k) : __ldg(WR1 + n * 64 + (k - 64));
        __half hi = __float2half_rn(v);
        __half lo = __float2half_rn(v - __half2float(hi));
        g_B1h[widx] = hi;
        g_B1l[widx] = lo;
        return;
    }
    if (widx < WTOT) {                          // layer 2, K = 256
        int j = widx - 128 * 128;
        int n = j >> 8, k = j & 255;
        float v = (k < 128) ? __ldg(WL2 + n * 128 + k) : __ldg(WR2 + n * 128 + (k - 128));
        __half hi = __float2half_rn(v);
        __half lo = __float2half_rn(v - __half2float(hi));
        g_B2h[j] = hi;
        g_B2l[j] = lo;
        return;
    }
    // ---- edge scatter ----
    int t  = idx - NCVT - WTOT;
    int e0 = t * 4;
    if (e0 >= E) return;
    int s[4], d[4], cnt;
    if (((E & 3) == 0) && (e0 + 3 < E)) {
        int4 s4 = __ldg(reinterpret_cast<const int4*>(ei) + t);
        int4 d4 = __ldg(reinterpret_cast<const int4*>(ei + E) + t);
        s[0] = s4.x; s[1] = s4.y; s[2] = s4.z; s[3] = s4.w;
        d[0] = d4.x; d[1] = d4.y; d[2] = d4.z; d[3] = d4.w;
        cnt = 4;
    } else {
        cnt = E - e0;
        if (cnt > 4) cnt = 4;
        for (int j = 0; j < cnt; ++j) {
            s[j] = __ldg(ei + e0 + j);
            d[j] = __ldg(ei + E + e0 + j);
        }
    }
#pragma unroll
    for (int j = 0; j < 4; ++j) {
        if (j < cnt) {
            int rank = atomicAdd(&g_deg[d[j]], 1);
            if (rank < ELL_W)
                g_ell[(size_t)d[j] * ELL_W + rank] = s[j];
        }
    }
}

// ---------------------------------------------------------------------------
// FUSED gather + GEMM (layer 1 only: 98KB smem -> 2 CTA/SM).
//   A (virtual, K=128 halfs) = [mean(x neighbors) | x]; mean gathered in-kernel
//   into smem; root half + all B via cp.async (overlaps the gather).
// ---------------------------------------------------------------------------
template <int K, bool LAYER1>
__global__ void __launch_bounds__(256)
sage_fused(const __half* __restrict__ Aroot,
           const __half* __restrict__ Bh,
           const __half* __restrict__ Bl,
           const float* __restrict__ bias,
           float* __restrict__ outF,
           __half* __restrict__ outH,
           int M) {
    constexpr int NT     = K / 64;
    constexpr int NMEAN  = NT / 2;
    constexpr int CH     = (K / 2) / 8;
    constexpr int ABYTES = NT * 16384;

    extern __shared__ char smem[];
    const uint32_t sbase = smem_u32(smem);

    const int tid     = threadIdx.x;
    const int block_m = blockIdx.x * 128;
    const int warp    = tid >> 5;
    const int lane    = tid & 31;
    const int wm      = warp & 3;
    const int wn      = warp >> 2;

    // ---- 1. cp.async: root-half A stages ----
#pragma unroll
    for (int kt = NMEAN; kt < NT; ++kt) {
        char* dst = smem + kt * 16384;
        const int colb = (kt - NMEAN) * 128;
#pragma unroll
        for (int j = 0; j < 4; ++j) {
            int c = j * 256 + tid;
            int row = c >> 3, ch = c & 7;
            int grow = block_m + row;
            if (grow >= M) grow = M - 1;
            const char* src = reinterpret_cast<const char*>(Aroot) +
                              (size_t)grow * K + colb + ch * 16;
            int off = row * 128 + ((ch ^ (row & 7)) << 4);
            CP_ASYNC16(smem_u32(dst + off), src);
        }
    }
    // ---- 2. cp.async: all B stages (hi + lo) ----
#pragma unroll
    for (int kt = 0; kt < NT; ++kt) {
        char* dst = smem + ABYTES + kt * 32768;
#pragma unroll
        for (int j = 0; j < 4; ++j) {
            int c = j * 256 + tid;
            int n = c >> 3, ch = c & 7;
            int off = n * 128 + ((ch ^ (n & 7)) << 4);
            const char* sh = reinterpret_cast<const char*>(Bh) +
                             (size_t)n * 2 * K + kt * 128 + ch * 16;
            CP_ASYNC16(smem_u32(dst + off), sh);
            const char* sl = reinterpret_cast<const char*>(Bl) +
                             (size_t)n * 2 * K + kt * 128 + ch * 16;
            CP_ASYNC16(smem_u32(dst + 16384 + off), sl);
        }
    }
    CP_COMMIT();

    // ---- 3. gather mean half into A smem (overlaps the cp.asyncs) ----
    {
        const uint4* srcU4 = reinterpret_cast<const uint4*>(Aroot);
#pragma unroll
        for (int it = 0; it < (128 * CH) / 256; ++it) {
            int item = it * 256 + tid;
            int row = item / CH;
            int c   = item % CH;
            int n = block_m + row;
            if (n >= M) n = M - 1;
            int dg  = __ldg(g_deg + n);
            int cnt2 = dg < ELL_W ? dg : ELL_W;
            const int* erow = g_ell + (size_t)n * ELL_W;

            float acc[8];
#pragma unroll
            for (int j = 0; j < 8; ++j) acc[j] = 0.f;

            auto accum = [&](uint4 v) {
                const __half2* p = reinterpret_cast<const __half2*>(&v);
#pragma unroll
                for (int w = 0; w < 4; ++w) {
                    float2 f = __half22float2(p[w]);
                    acc[2 * w + 0] += f.x;
                    acc[2 * w + 1] += f.y;
                }
            };

            int i = 0;
            for (; i + 4 <= cnt2; i += 4) {
                int s0 = __ldg(erow + i),     s1 = __ldg(erow + i + 1);
                int s2 = __ldg(erow + i + 2), s3 = __ldg(erow + i + 3);
                uint4 v0 = __ldg(srcU4 + (size_t)s0 * CH + c);
                uint4 v1 = __ldg(srcU4 + (size_t)s1 * CH + c);
                uint4 v2 = __ldg(srcU4 + (size_t)s2 * CH + c);
                uint4 v3 = __ldg(srcU4 + (size_t)s3 * CH + c);
                accum(v0); accum(v1); accum(v2); accum(v3);
            }
            for (; i < cnt2; ++i)
                accum(__ldg(srcU4 + (size_t)__ldg(erow + i) * CH + c));

            float inv = 1.0f / fmaxf((float)dg, 1.0f);
            uint4 o;
            __half2* p = reinterpret_cast<__half2*>(&o);
#pragma unroll
            for (int w = 0; w < 4; ++w)
                p[w] = __floats2half2_rn(acc[2 * w] * inv, acc[2 * w + 1] * inv);

            int kt = c >> 3, ch = c & 7;
            *reinterpret_cast<uint4*>(
                smem + kt * 16384 + row * 128 + ((ch ^ (row & 7)) << 4)) = o;
        }
    }

    CP_WAIT(0);
    __syncthreads();

    // ---- 4. mainloop ----
    float d[2][8][4];
#pragma unroll
    for (int i = 0; i < 2; ++i)
#pragma unroll
        for (int j = 0; j < 8; ++j)
#pragma unroll
            for (int q = 0; q < 4; ++q) d[i][j][q] = 0.f;

#pragma unroll
    for (int kt = 0; kt < NT; ++kt) {
        const uint32_t sA  = sbase + kt * 16384;
        const uint32_t sBh = sbase + ABYTES + kt * 32768;
        const uint32_t sBl = sBh + 16384;

#pragma unroll
        for (int kk = 0; kk < 4; ++kk) {
            uint32_t a[2][4];
#pragma unroll
            for (int mt = 0; mt < 2; ++mt) {
                int row = wm * 32 + mt * 16 + (lane & 15);
                int ch  = kk * 2 + (lane >> 4);
                int off = row * 128 + ((ch ^ (row & 7)) << 4);
                LDSM4(a[mt][0], a[mt][1], a[mt][2], a[mt][3], sA + off);
            }
            uint32_t bh[4][4], bl[4][4];
#pragma unroll
            for (int nt2 = 0; nt2 < 4; ++nt2) {
                int row = wn * 64 + nt2 * 16 + (lane & 15);
                int ch  = kk * 2 + (lane >> 4);
                int off = row * 128 + ((ch ^ (row & 7)) << 4);
                LDSM4(bh[nt2][0], bh[nt2][1], bh[nt2][2], bh[nt2][3], sBh + off);
                LDSM4(bl[nt2][0], bl[nt2][1], bl[nt2][2], bl[nt2][3], sBl + off);
            }
#pragma unroll
            for (int mt = 0; mt < 2; ++mt)
#pragma unroll
                for (int nt = 0; nt < 8; ++nt) {
                    int nt2 = nt >> 1, o = nt & 1;
                    MMA16816F(d[mt][nt], a[mt], bh[nt2][o], bh[nt2][o + 2]);
                    MMA16816F(d[mt][nt], a[mt], bl[nt2][o], bl[nt2][o + 2]);
                }
        }
    }

    // ---- 5. epilogue ----
    const int r0base = block_m + wm * 32 + (lane >> 2);
    const int cbase  = wn * 64 + (lane & 3) * 2;
#pragma unroll
    for (int mt = 0; mt < 2; ++mt) {
#pragma unroll
        for (int nt = 0; nt < 8; ++nt) {
            int c = cbase + nt * 8;
            float b0 = __ldg(bias + c);
            float b1 = __ldg(bias + c + 1);
#pragma unroll
            for (int half = 0; half < 2; ++half) {
                int row = r0base + mt * 16 + half * 8;
                if (row >= M) continue;
                float o0 = d[mt][nt][half * 2 + 0] + b0;
                float o1 = d[mt][nt][half * 2 + 1] + b1;
                if (LAYER1) {
                    o0 = fmaxf(o0, 0.f);
                    o1 = fmaxf(o1, 0.f);
                    *reinterpret_cast<__half2*>(outH + (size_t)row * 128 + c) =
                        __floats2half2_rn(o0, o1);
                } else {
                    *reinterpret_cast<float2*>(outF + (size_t)row * 128 + c) =
                        make_float2(o0, o1);
                }
            }
        }
    }
}

// ---------------------------------------------------------------------------
// Standalone fp16 gather-reduce (mean) for layer 2 (proven R15 version)
// ---------------------------------------------------------------------------
template <int FQ>
__global__ void gather_mean_f16(const uint4* __restrict__ srcH,
                                __half* __restrict__ outm) {
    int idx = blockIdx.x * blockDim.x + threadIdx.x;
    int n = idx / FQ;
    if (n >= N_NODES) return;
    int q = idx % FQ;
    int dg  = __ldg(g_deg + n);
    int cnt = dg < ELL_W ? dg : ELL_W;
    const int* row = g_ell + (size_t)n * ELL_W;

    float acc[8];
#pragma unroll
    for (int j = 0; j < 8; ++j) acc[j] = 0.f;

    auto accum = [&](uint4 v) {
        const __half2* p = reinterpret_cast<const __half2*>(&v);
#pragma unroll
        for (int w = 0; w < 4; ++w) {
            float2 f = __half22float2(p[w]);
            acc[2 * w + 0] += f.x;
            acc[2 * w + 1] += f.y;
        }
    };

    int i = 0;
    for (; i + 8 <= cnt; i += 8) {
        int sidx[8];
#pragma unroll
        for (int j = 0; j < 8; ++j) sidx[j] = __ldg(row + i + j);
        uint4 v[8];
#pragma unroll
        for (int j = 0; j < 8; ++j) v[j] = __ldg(srcH + (size_t)sidx[j] * FQ + q);
#pragma unroll
        for (int j = 0; j < 8; ++j) accum(v[j]);
    }
    if (i + 4 <= cnt) {
        int s0 = __ldg(row + i),     s1 = __ldg(row + i + 1);
        int s2 = __ldg(row + i + 2), s3 = __ldg(row + i + 3);
        uint4 v0 = __ldg(srcH + (size_t)s0 * FQ + q);
        uint4 v1 = __ldg(srcH + (size_t)s1 * FQ + q);
        uint4 v2 = __ldg(srcH + (size_t)s2 * FQ + q);
        uint4 v3 = __ldg(srcH + (size_t)s3 * FQ + q);
        accum(v0); accum(v1); accum(v2); accum(v3);
        i += 4;
    }
    for (; i < cnt; ++i)
        accum(__ldg(srcH + (size_t)__ldg(row + i) * FQ + q));

    float inv = 1.0f / fmaxf((float)dg, 1.0f);

    uint4 o;
    __half2* p = reinterpret_cast<__half2*>(&o);
#pragma unroll
    for (int w = 0; w < 4; ++w)
        p[w] = __floats2half2_rn(acc[2 * w] * inv, acc[2 * w + 1] * inv);
    *reinterpret_cast<uint4*>(outm + ((size_t)n * FQ + q) * 8) = o;
}

// ---------------------------------------------------------------------------
// Unfused f16 MMA GEMM (layer 2; proven R15 version)
// ---------------------------------------------------------------------------
template <int K, bool LAYER1>
__global__ void __launch_bounds__(256)
sage_gemm_mma(const __half* __restrict__ Am,
              const __half* __restrict__ Ar,
              const __half* __restrict__ Bh,
              const __half* __restrict__ Bl,
              const float* __restrict__ bias,
              float* __restrict__ outF,
              __half* __restrict__ outH,
              int M) {
    constexpr int BK  = 64;
    constexpr int NT  = K / BK;
    constexpr int KH  = K / 2;
    constexpr int STG = 49152;

    extern __shared__ char smem[];
    const uint32_t sbase = smem_u32(smem);

    const int tid     = threadIdx.x;
    const int block_m = blockIdx.x * 128;
    const int warp    = tid >> 5;
    const int lane    = tid & 31;
    const int wm      = warp & 3;
    const int wn      = warp >> 2;

    auto issue_stage = [&](int kt) {
        char* dst = smem + (kt & 1) * STG;
        const bool mean = kt < (NT / 2);
        const __half* Asrc = mean ? Am : Ar;
        const int colb = (mean ? kt : kt - NT / 2) * 128;
#pragma unroll
        for (int j = 0; j < 4; ++j) {
            int c = j * 256 + tid;
            int row = c >> 3, ch = c & 7;
            int grow = block_m + row;
            if (grow >= M) grow = M - 1;
            const char* src = reinterpret_cast<const char*>(Asrc) +
                              (size_t)grow * (2 * KH) + colb + ch * 16;
            int off = row * 128 + ((ch ^ (row & 7)) << 4);
            CP_ASYNC16(smem_u32(dst + off), src);
        }
#pragma unroll
        for (int j = 0; j < 4; ++j) {
            int c = j * 256 + tid;
            int n = c >> 3, ch = c & 7;
            int off = n * 128 + ((ch ^ (n & 7)) << 4);
            const char* sh = reinterpret_cast<const char*>(Bh) +
                             (size_t)n * 2 * K + kt * 128 + ch * 16;
            CP_ASYNC16(smem_u32(dst + 16384 + off), sh);
            const char* sl = reinterpret_cast<const char*>(Bl) +
                             (size_t)n * 2 * K + kt * 128 + ch * 16;
            CP_ASYNC16(smem_u32(dst + 32768 + off), sl);
        }
        CP_COMMIT();
    };

    float d[2][8][4];
#pragma unroll
    for (int i = 0; i < 2; ++i)
#pragma unroll
        for (int j = 0; j < 8; ++j)
#pragma unroll
            for (int q = 0; q < 4; ++q) d[i][j][q] = 0.f;

    issue_stage(0);

    for (int kt = 0; kt < NT; ++kt) {
        if (kt + 1 < NT) {
            issue_stage(kt + 1);
            CP_WAIT(1);
        } else {
            CP_WAIT(0);
        }
        __syncthreads();

        const uint32_t sA  = sbase + (kt & 1) * STG;
        const uint32_t sBh = sA + 16384;
        const uint32_t sBl = sA + 32768;

#pragma unroll
        for (int kk = 0; kk < 4; ++kk) {
            uint32_t a[2][4];
#pragma unroll
            for (int mt = 0; mt < 2; ++mt) {
                int row = wm * 32 + mt * 16 + (lane & 15);
                int ch  = kk * 2 + (lane >> 4);
                int off = row * 128 + ((ch ^ (row & 7)) << 4);
                LDSM4(a[mt][0], a[mt][1], a[mt][2], a[mt][3], sA + off);
            }
            uint32_t bh[4][4], bl[4][4];
#pragma unroll
            for (int nt2 = 0; nt2 < 4; ++nt2) {
                int row = wn * 64 + nt2 * 16 + (lane & 15);
                int ch  = kk * 2 + (lane >> 4);
                int off = row * 128 + ((ch ^ (row & 7)) << 4);
                LDSM4(bh[nt2][0], bh[nt2][1], bh[nt2][2], bh[nt2][3], sBh + off);
                LDSM4(bl[nt2][0], bl[nt2][1], bl[nt2][2], bl[nt2][3], sBl + off);
            }
#pragma unroll
            for (int mt = 0; mt < 2; ++mt)
#pragma unroll
                for (int nt = 0; nt < 8; ++nt) {
                    int nt2 = nt >> 1, o = nt & 1;
                    MMA16816F(d[mt][nt], a[mt], bh[nt2][o], bh[nt2][o + 2]);
                    MMA16816F(d[mt][nt], a[mt], bl[nt2][o], bl[nt2][o + 2]);
                }
        }
        __syncthreads();
    }

    const int r0base = block_m + wm * 32 + (lane >> 2);
    const int cbase  = wn * 64 + (lane & 3) * 2;
#pragma unroll
    for (int mt = 0; mt < 2; ++mt) {
#pragma unroll
        for (int nt = 0; nt < 8; ++nt) {
            int c = cbase + nt * 8;
            float b0 = __ldg(bias + c);
            float b1 = __ldg(bias + c + 1);
#pragma unroll
            for (int half = 0; half < 2; ++half) {
                int row = r0base + mt * 16 + half * 8;
                if (row >= M) continue;
                float o0 = d[mt][nt][half * 2 + 0] + b0;
                float o1 = d[mt][nt][half * 2 + 1] + b1;
                if (LAYER1) {
                    o0 = fmaxf(o0, 0.f);
                    o1 = fmaxf(o1, 0.f);
                    *reinterpret_cast<__half2*>(outH + (size_t)row * 128 + c) =
                        __floats2half2_rn(o0, o1);
                } else {
                    *reinterpret_cast<float2*>(outF + (size_t)row * 128 + c) =
                        make_float2(o0, o1);
                }
            }
        }
    }
}

// ---------------------------------------------------------------------------
extern "C" void kernel_launch(void* const* d_in, const int* in_sizes, int n_in,
                              void* d_out, int out_size) {
    const float* x   = (const float*)d_in[0];
    const int*   ei  = (const int*)  d_in[1];
    const float* Wl1 = (const float*)d_in[2];
    const float* bl1 = (const float*)d_in[3];
    const float* Wr1 = (const float*)d_in[4];
    const float* Wl2 = (const float*)d_in[5];
    const float* bl2 = (const float*)d_in[6];
    const float* Wr2 = (const float*)d_in[7];
    float* out = (float*)d_out;

    const int E = in_sizes[1] / 2;
    const int M = N_NODES;

    __half *xf, *hf, *m2, *b1h, *b1l, *b2h, *b2l;
    cudaGetSymbolAddress((void**)&xf,  g_xf);
    cudaGetSymbolAddress((void**)&hf,  g_hf);
    cudaGetSymbolAddress((void**)&m2,  g_m2);
    cudaGetSymbolAddress((void**)&b1h, g_B1h);
    cudaGetSymbolAddress((void**)&b1l, g_B1l);
    cudaGetSymbolAddress((void**)&b2h, g_B2h);
    cudaGetSymbolAddress((void**)&b2l, g_B2l);

    static bool attr_done = false;
    if (!attr_done) {
        cudaFuncSetAttribute(sage_fused<128, true>,
                             cudaFuncAttributeMaxDynamicSharedMemorySize, 98304);
        cudaFuncSetAttribute(sage_gemm_mma<256, false>,
                             cudaFuncAttributeMaxDynamicSharedMemorySize, 98304);
        attr_done = true;
    }

    const int gemm_blocks = (M + 127) / 128;
    const long pb_threads = (long)NCVT + WTOT + (E + 3) / 4;

    zero_deg<<<(N_NODES + 255) / 256, 256>>>();
    prep_build<<<(pb_threads + 255) / 256, 256>>>(
        reinterpret_cast<const float4*>(x), xf, Wl1, Wr1, Wl2, Wr2, ei, E);

    // layer 1: fused gather + GEMM (2 CTA/SM)
    sage_fused<128, true><<<gemm_blocks, 256, 98304>>>(
        xf, b1h, b1l, bl1, nullptr, hf, M);

    // layer 2: separate gather + GEMM (both near floor)
    gather_mean_f16<16><<<((long)M * 16 + 255) / 256, 256>>>(
        reinterpret_cast<const uint4*>(hf), m2);
    sage_gemm_mma<256, false><<<gemm_blocks, 256, 98304>>>(
        m2, hf, b2h, b2l, bl2, out, nullptr, M);
}